// round 8
// baseline (speedup 1.0000x reference)
#include <cuda_runtime.h>
#include <cuda_bf16.h>
#include <math.h>
#include <stdint.h>

#define BATCH 16
#define LSP   4096
#define DD    512
#define UTOP  450
#define SCALE 0.044194173824159216f
#define P2M   ((size_t)LSP * DD)
typedef __nv_bfloat16 bf16;
typedef uint32_t u32;

#define PITCHB  144        // 64 bf16 + 8 pad = 72 bf16 = 144B row pitch
#define PLANE_S 18432      // 128 rows * 144B
#define SMTOT   (6 * PLANE_S)

// ---------------- scratch ----------------
__device__ float g_V[(size_t)BATCH * P2M];
__device__ bf16  g_Ws[3 * 3 * 262144];
__device__ bf16  g_Xt[(size_t)BATCH * 3 * P2M];
__device__ bf16  g_Qs[(size_t)BATCH * 3 * P2M];
__device__ bf16  g_Ksp[(size_t)BATCH * 3 * P2M];
__device__ bf16  g_Vt[(size_t)BATCH * 2 * P2M];
__device__ bf16  g_Kss[(size_t)BATCH * 3 * 262144];
__device__ bf16  g_Qrs[(size_t)BATCH * 3 * 262144];
__device__ bf16  g_Attn[(size_t)BATCH * 2 * P2M];
__device__ float g_Scores[(size_t)BATCH * UTOP * LSP];
__device__ float g_MpMax[BATCH * 4 * LSP];
__device__ float g_MpSum[BATCH * 4 * LSP];
__device__ int   g_selrank[BATCH * LSP];
__device__ int   g_mtop[BATCH * UTOP];
__device__ float g_Upd[(size_t)BATCH * UTOP * DD];
__device__ float g_Vpart[BATCH * 4 * DD];
__device__ float g_Vmean[BATCH * DD];

// ---------------- helpers ----------------
__device__ __forceinline__ void split3(float x, bf16& c0, bf16& c1, bf16& c2) {
  c0 = __float2bfloat16(x);
  float r = x - __bfloat162float(c0);
  c1 = __float2bfloat16(r);
  r -= __bfloat162float(c1);
  c2 = __float2bfloat16(r);
}
__device__ __forceinline__ void split2(float x, bf16& c0, bf16& c1) {
  c0 = __float2bfloat16(x);
  c1 = __float2bfloat16(x - __bfloat162float(c0));
}
__device__ __forceinline__ u32 smem_u32(const void* p) {
  u32 a;
  asm("{ .reg .u64 t; cvta.to.shared.u64 t, %1; cvt.u32.u64 %0, t; }" : "=r"(a) : "l"(p));
  return a;
}
__device__ __forceinline__ void ldm4(u32* r, u32 addr) {
  asm volatile("ldmatrix.sync.aligned.m8n8.x4.shared.b16 {%0,%1,%2,%3}, [%4];"
               : "=r"(r[0]), "=r"(r[1]), "=r"(r[2]), "=r"(r[3]) : "r"(addr));
}
__device__ __forceinline__ void mma16816(float* c, const u32* a, const u32* b) {
  asm volatile(
      "mma.sync.aligned.m16n8k16.row.col.f32.bf16.bf16.f32 "
      "{%0,%1,%2,%3}, {%4,%5,%6,%7}, {%8,%9}, {%0,%1,%2,%3};"
      : "+f"(c[0]), "+f"(c[1]), "+f"(c[2]), "+f"(c[3])
      : "r"(a[0]), "r"(a[1]), "r"(a[2]), "r"(a[3]), "r"(b[0]), "r"(b[1]));
}
__device__ __forceinline__ float fast_exp(float x) {
  x = fmaxf(x, -80.0f);
  float t = x * 1.4426950408889634f, r = rintf(t), f = t - r;
  float p = 1.5404e-4f;
  p = fmaf(p, f, 1.33336e-3f); p = fmaf(p, f, 9.61813e-3f);
  p = fmaf(p, f, 5.55041e-2f); p = fmaf(p, f, 2.40227e-1f);
  p = fmaf(p, f, 6.93147181e-1f); p = fmaf(p, f, 1.0f);
  return __int_as_float(__float_as_int(p) + (((int)r) << 23));
}

// ---------------- mma.sync GEMM (MODE 0 proj, 1 qks->M, 2 scores, 3 upd) ----
template <int MODE>
__global__ void __launch_bounds__(256) mma_kernel(const float* __restrict__ bq,
                                                  const float* __restrict__ bk,
                                                  const float* __restrict__ bv) {
  extern __shared__ char smem[];
  const int tid = threadIdx.x, lane = tid & 31, wid = tid >> 5;
  const int wm = wid & 1, wn = wid >> 1;       // 2 x 4 warp grid
  const int b = blockIdx.z;
  constexpr int NC = (MODE <= 1) ? 3 : 2;
  constexpr int NCOMBO = (MODE <= 1) ? 6 : 3;
  constexpr int CI[6] = {0, 0, 1, 1, 2, 0};
  constexpr int CJ[6] = {0, 1, 0, 1, 0, 2};

  int rowA0, wsel = 0, nCh;
  size_t aPlane, bPlane, apit, bpit;
  const bf16 *Ab, *Bb;
  if (MODE == 0) {
    wsel = blockIdx.y >> 2; rowA0 = (blockIdx.y & 3) * 128;
    Ab = g_Ws + (size_t)wsel * 3 * 262144; aPlane = 262144; apit = 512;
    Bb = g_Xt + (size_t)b * 3 * P2M; bPlane = P2M; bpit = 512; nCh = 8;
  } else if (MODE == 1) {
    rowA0 = blockIdx.y * 128;
    Ab = g_Qs + (size_t)b * 3 * P2M; aPlane = P2M; apit = 512;
    Bb = g_Kss + (size_t)b * 3 * 262144; bPlane = 262144; bpit = 512; nCh = 8;
  } else if (MODE == 2) {
    rowA0 = blockIdx.y * 128;
    Ab = g_Qrs + (size_t)b * 3 * 262144; aPlane = 262144; apit = 512;
    Bb = g_Ksp + (size_t)b * 3 * P2M; bPlane = P2M; bpit = 512; nCh = 8;
  } else {
    rowA0 = blockIdx.y * 128;
    Ab = g_Attn + (size_t)b * 2 * P2M; aPlane = P2M; apit = 4096;
    Bb = g_Vt + (size_t)b * 2 * P2M; bPlane = P2M; bpit = 4096; nCh = 64;
  }
  const int rowB0 = blockIdx.x * 128;
  const u32 sb = smem_u32(smem);

  float acc[4][4][4] = {};
  const int srow = tid >> 1, shalf = tid & 1;

  for (int ch = 0; ch < nCh; ch++) {
    const int kt = ch * 64;
    // stage: 128 rows x 64 bf16 per plane; thread: row=tid/2, half=tid&1 (32 bf16 = 64B)
    #pragma unroll
    for (int c = 0; c < NC; c++) {
      const char* ga = (const char*)(Ab + (size_t)c * aPlane + (size_t)(rowA0 + srow) * apit + kt + shalf * 32);
      char* sa = smem + c * PLANE_S + srow * PITCHB + shalf * 64;
      const char* gb = (const char*)(Bb + (size_t)c * bPlane + (size_t)(rowB0 + srow) * bpit + kt + shalf * 32);
      char* sbp = smem + (3 + c) * PLANE_S + srow * PITCHB + shalf * 64;
      #pragma unroll
      for (int i = 0; i < 4; i++) {
        *(uint4*)(sa + i * 16) = *(const uint4*)(ga + i * 16);
        *(uint4*)(sbp + i * 16) = *(const uint4*)(gb + i * 16);
      }
    }
    __syncthreads();

    #pragma unroll
    for (int kk = 0; kk < 4; kk++) {
      const int k0 = kk * 16;
      u32 afr[NC][4][4], bfr[NC][4][2];
      #pragma unroll
      for (int c = 0; c < NC; c++) {
        #pragma unroll
        for (int mt = 0; mt < 4; mt++) {
          u32 ad = sb + c * PLANE_S + (wm * 64 + mt * 16 + (lane & 15)) * PITCHB +
                   k0 * 2 + (lane >> 4) * 16;
          ldm4(afr[c][mt], ad);
        }
        #pragma unroll
        for (int p = 0; p < 2; p++) {
          u32 bd = sb + (3 + c) * PLANE_S +
                   (wn * 32 + p * 16 + (lane & 7) + ((lane >> 4) & 1) * 8) * PITCHB +
                   k0 * 2 + ((lane >> 3) & 1) * 16;
          u32 t4[4]; ldm4(t4, bd);
          bfr[c][2 * p][0] = t4[0]; bfr[c][2 * p][1] = t4[1];
          bfr[c][2 * p + 1][0] = t4[2]; bfr[c][2 * p + 1][1] = t4[3];
        }
      }
      #pragma unroll
      for (int q = 0; q < NCOMBO; q++) {
        #pragma unroll
        for (int mt = 0; mt < 4; mt++)
          #pragma unroll
          for (int nt = 0; nt < 4; nt++)
            mma16816(acc[mt][nt], afr[CI[q]][mt], bfr[CJ[q]][nt]);
      }
    }
    __syncthreads();
  }

  const int qrow = lane >> 2, qcol = (lane & 3) * 2;

  if (MODE == 1) {
    // per-thread reduce over its 8 s-cols for each of its 8 l-rows
    float mx[8], sm[8];
    #pragma unroll
    for (int i = 0; i < 8; i++) { mx[i] = -3.0e38f; sm[i] = 0.f; }
    #pragma unroll
    for (int mt = 0; mt < 4; mt++)
      #pragma unroll
      for (int h = 0; h < 2; h++)
        #pragma unroll
        for (int nt = 0; nt < 4; nt++)
          #pragma unroll
          for (int e = 0; e < 2; e++) {
            int s = rowB0 + wn * 32 + nt * 8 + qcol + e;
            float v = acc[mt][nt][h * 2 + e];
            if (s < UTOP) { mx[mt * 2 + h] = fmaxf(mx[mt * 2 + h], v); sm[mt * 2 + h] += v; }
          }
    #pragma unroll
    for (int off = 1; off <= 2; off <<= 1)
      #pragma unroll
      for (int i = 0; i < 8; i++) {
        mx[i] = fmaxf(mx[i], __shfl_xor_sync(0xffffffffu, mx[i], off));
        sm[i] += __shfl_xor_sync(0xffffffffu, sm[i], off);
      }
    float* smax = (float*)smem;          // [128][4]
    float* ssum = smax + 512;
    if ((lane & 3) == 0) {
      #pragma unroll
      for (int mt = 0; mt < 4; mt++)
        #pragma unroll
        for (int h = 0; h < 2; h++) {
          int rl = wm * 64 + mt * 16 + qrow + h * 8;
          smax[rl * 4 + wn] = mx[mt * 2 + h];
          ssum[rl * 4 + wn] = sm[mt * 2 + h];
        }
    }
    __syncthreads();
    if (tid < 128) {
      float M1 = -3.0e38f, S = 0.f;
      #pragma unroll
      for (int j = 0; j < 4; j++) { M1 = fmaxf(M1, smax[tid * 4 + j]); S += ssum[tid * 4 + j]; }
      g_MpMax[((size_t)b * 4 + blockIdx.x) * LSP + rowA0 + tid] = M1;
      g_MpSum[((size_t)b * 4 + blockIdx.x) * LSP + rowA0 + tid] = S;
    }
    return;
  }

  #pragma unroll
  for (int mt = 0; mt < 4; mt++) {
    #pragma unroll
    for (int h = 0; h < 2; h++) {
      const int m = rowA0 + wm * 64 + mt * 16 + qrow + h * 8;
      float bias_v = 0.f;
      if (MODE == 0) bias_v = (wsel == 0 ? bq : wsel == 1 ? bk : bv)[m & 511];
      #pragma unroll
      for (int nt = 0; nt < 4; nt++) {
        const int col = rowB0 + wn * 32 + nt * 8 + qcol;
        float v0 = acc[mt][nt][h * 2 + 0];
        float v1 = acc[mt][nt][h * 2 + 1];
        if (MODE == 0) {
          v0 += bias_v; v1 += bias_v;
          size_t flat = (size_t)m * 4096 + col;
          if (wsel == 2) {
            *(float2*)(g_V + (size_t)b * P2M + flat) = make_float2(v0, v1);
          } else {
            bf16* qp = (wsel == 0 ? g_Qs : g_Ksp) + (size_t)b * 3 * P2M;
            bf16 a0, a1, a2, c0, c1, c2;
            split3(v0, a0, a1, a2); split3(v1, c0, c1, c2);
            *(__nv_bfloat162*)(qp + flat) = __halves2bfloat162(a0, c0);
            *(__nv_bfloat162*)(qp + P2M + flat) = __halves2bfloat162(a1, c1);
            *(__nv_bfloat162*)(qp + 2 * P2M + flat) = __halves2bfloat162(a2, c2);
          }
        } else if (MODE == 2) {
          if (m < UTOP)
            *(float2*)(g_Scores + ((size_t)b * UTOP + m) * LSP + col) =
                make_float2(v0 * SCALE, v1 * SCALE);
        } else {
          if (m < UTOP)
            *(float2*)(g_Upd + ((size_t)b * UTOP + m) * DD + col) = make_float2(v0, v1);
        }
      }
    }
  }
}

// ---------------- prep kernels ----------------
__global__ void wsplit_kernel(const float* __restrict__ Wq, const float* __restrict__ Wk,
                              const float* __restrict__ Wv) {
  int mat = blockIdx.y;
  int i = blockIdx.x * 1024 + threadIdx.x;
  const float* W = mat == 0 ? Wq : mat == 1 ? Wk : Wv;
  bf16 c0, c1, c2; split3(W[i], c0, c1, c2);
  bf16* o = g_Ws + (size_t)mat * 3 * 262144;
  o[i] = c0; o[262144 + i] = c1; o[2 * 262144 + i] = c2;
}

__global__ void xt_split_kernel(const float* __restrict__ in1, const float* __restrict__ in2) {
  __shared__ float t[32][33];
  int b = blockIdx.z, c0i = blockIdx.y * 32, sp0 = blockIdx.x * 32;
  for (int j = threadIdx.y; j < 32; j += 8) {
    int c = c0i + j;
    const float* s = (c < 256) ? in1 + ((size_t)b * 256 + c) * LSP
                               : in2 + ((size_t)b * 256 + (c - 256)) * LSP;
    t[j][threadIdx.x] = s[sp0 + threadIdx.x];
  }
  __syncthreads();
  bf16* o = g_Xt + (size_t)b * 3 * P2M;
  for (int j = threadIdx.y; j < 32; j += 8) {
    size_t flat = (size_t)(sp0 + j) * 512 + c0i + threadIdx.x;
    bf16 a0, a1, a2; split3(t[threadIdx.x][j], a0, a1, a2);
    o[flat] = a0; o[P2M + flat] = a1; o[2 * P2M + flat] = a2;
  }
}

__global__ void vt_split_kernel() {
  __shared__ float t[32][33];
  int b = blockIdx.z, l0 = blockIdx.x * 32, d0 = blockIdx.y * 32;
  const float* V = g_V + (size_t)b * P2M;
  for (int j = threadIdx.y; j < 32; j += 8)
    t[j][threadIdx.x] = V[(size_t)(l0 + j) * 512 + d0 + threadIdx.x];
  __syncthreads();
  bf16* o = g_Vt + (size_t)b * 2 * P2M;
  for (int j = threadIdx.y; j < 32; j += 8) {
    size_t flat = (size_t)(d0 + j) * LSP + l0 + threadIdx.x;
    bf16 a0, a1; split2(t[threadIdx.x][j], a0, a1);
    o[flat] = a0; o[P2M + flat] = a1;
  }
}

__global__ void gather_ks3_kernel(const int* __restrict__ idx) {
  int b = blockIdx.y, s = blockIdx.x, t = threadIdx.x;
  int l = idx[s];
  int c = t >> 6, i = t & 63;
  const uint4* src = (const uint4*)(g_Ksp + ((size_t)b * 3 + c) * P2M + (size_t)l * 512);
  uint4* dst = (uint4*)(g_Kss + ((size_t)b * 3 + c) * 262144 + (size_t)s * 512);
  dst[i] = src[i];
}
__global__ void gather_qr3_kernel() {
  int b = blockIdx.y, s = blockIdx.x, t = threadIdx.x;
  int l = g_mtop[b * UTOP + s];
  int c = t >> 6, i = t & 63;
  const uint4* src = (const uint4*)(g_Qs + ((size_t)b * 3 + c) * P2M + (size_t)l * 512);
  uint4* dst = (uint4*)(g_Qrs + ((size_t)b * 3 + c) * 262144 + (size_t)s * 512);
  dst[i] = src[i];
}

// ---------------- topk (reduces MODE1 partials) ----------------
__global__ __launch_bounds__(1024) void topk_kernel() {
  const int b = blockIdx.x, tid = threadIdx.x;
  __shared__ unsigned long long keys[4096];
  for (int i = tid; i < 4096; i += 1024) {
    float mx = -3.0e38f, sm = 0.f;
    #pragma unroll
    for (int st = 0; st < 4; st++) {
      mx = fmaxf(mx, g_MpMax[((size_t)b * 4 + st) * LSP + i]);
      sm += g_MpSum[((size_t)b * 4 + st) * LSP + i];
    }
    float M = mx - sm * (1.0f / 4096.0f);
    unsigned u = __float_as_uint(M);
    u = (u & 0x80000000u) ? ~u : (u | 0x80000000u);
    keys[i] = ((unsigned long long)(~u) << 32) | (unsigned)i;
  }
  __syncthreads();
  for (int k = 2; k <= 4096; k <<= 1)
    for (int j = k >> 1; j > 0; j >>= 1) {
      for (int t = tid; t < 4096; t += 1024) {
        int ixj = t ^ j;
        if (ixj > t) {
          unsigned long long a = keys[t], c = keys[ixj];
          bool up = ((t & k) == 0);
          if ((a > c) == up) { keys[t] = c; keys[ixj] = a; }
        }
      }
      __syncthreads();
    }
  for (int i = tid; i < 4096; i += 1024) g_selrank[b * LSP + i] = -1;
  __syncthreads();
  if (tid < UTOP) {
    int l = (int)(unsigned)(keys[tid] & 0xffffffffu);
    g_selrank[b * LSP + l] = tid;
    g_mtop[b * UTOP + tid] = l;
  }
}

// ---------------- softmax + 2-comp attn split ----------------
__global__ __launch_bounds__(256) void softmax_kernel() {
  const int row = blockIdx.x, b = row / UTOP, u = row - b * UTOP;
  const float4* p = (const float4*)(g_Scores + (size_t)row * LSP);
  const int tid = threadIdx.x;
  __shared__ float red[256];
  float4 r[4];
  float m = -3.0e38f;
  #pragma unroll
  for (int i = 0; i < 4; i++) {
    r[i] = p[tid + i * 256];
    m = fmaxf(m, fmaxf(fmaxf(r[i].x, r[i].y), fmaxf(r[i].z, r[i].w)));
  }
  red[tid] = m; __syncthreads();
  for (int s = 128; s; s >>= 1) { if (tid < s) red[tid] = fmaxf(red[tid], red[tid + s]); __syncthreads(); }
  m = red[0]; __syncthreads();
  float sum = 0.f;
  #pragma unroll
  for (int i = 0; i < 4; i++) {
    r[i].x = fast_exp(r[i].x - m); r[i].y = fast_exp(r[i].y - m);
    r[i].z = fast_exp(r[i].z - m); r[i].w = fast_exp(r[i].w - m);
    sum += (r[i].x + r[i].y) + (r[i].z + r[i].w);
  }
  red[tid] = sum; __syncthreads();
  for (int s = 128; s; s >>= 1) { if (tid < s) red[tid] += red[tid + s]; __syncthreads(); }
  float inv = 1.0f / red[0];
  bf16* a0 = g_Attn + (size_t)b * 2 * P2M + (size_t)u * LSP;
  bf16* a1 = a0 + P2M;
  #pragma unroll
  for (int i = 0; i < 4; i++) {
    int c = (tid + i * 256) * 4;
    float v[4] = {r[i].x * inv, r[i].y * inv, r[i].z * inv, r[i].w * inv};
    bf16 lo[4], hi[4];
    #pragma unroll
    for (int k = 0; k < 4; k++) split2(v[k], lo[k], hi[k]);
    *(__nv_bfloat162*)(a0 + c) = __halves2bfloat162(lo[0], lo[1]);
    *(__nv_bfloat162*)(a0 + c + 2) = __halves2bfloat162(lo[2], lo[3]);
    *(__nv_bfloat162*)(a1 + c) = __halves2bfloat162(hi[0], hi[1]);
    *(__nv_bfloat162*)(a1 + c + 2) = __halves2bfloat162(hi[2], hi[3]);
  }
}

// ---------------- V mean + assemble ----------------
__global__ __launch_bounds__(512) void vpart_kernel() {
  const int b = blockIdx.y, g = blockIdx.x, d = threadIdx.x;
  const float* base = g_V + (size_t)b * P2M + (size_t)(g * 1024) * 512 + d;
  float s0 = 0, s1 = 0, s2 = 0, s3 = 0;
  for (int l = 0; l < 1024; l += 4) {
    s0 += base[(size_t)(l + 0) * 512]; s1 += base[(size_t)(l + 1) * 512];
    s2 += base[(size_t)(l + 2) * 512]; s3 += base[(size_t)(l + 3) * 512];
  }
  g_Vpart[((size_t)b * 4 + g) * 512 + d] = (s0 + s1) + (s2 + s3);
}
__global__ __launch_bounds__(512) void vmean_kernel() {
  const int b = blockIdx.x, d = threadIdx.x;
  float s = 0;
  #pragma unroll
  for (int g = 0; g < 4; g++) s += g_Vpart[((size_t)b * 4 + g) * 512 + d];
  g_Vmean[b * 512 + d] = s * (1.0f / 4096.0f);
}
__global__ void assemble_kernel(float* __restrict__ out) {
  const int b = blockIdx.y, l = blockIdx.x;
  const int r = g_selrank[b * LSP + l];
  const float4* src = (r >= 0) ? (const float4*)(g_Upd + ((size_t)b * UTOP + r) * 512)
                               : (const float4*)(g_Vmean + (size_t)b * 512);
  float4* dst = (float4*)(out + ((size_t)b * LSP + l) * 512);
  dst[threadIdx.x] = src[threadIdx.x];
}

// ---------------- launch ----------------
extern "C" void kernel_launch(void* const* d_in, const int* in_sizes, int n_in,
                              void* d_out, int out_size) {
  const float* in1 = (const float*)d_in[0];
  const float* in2 = (const float*)d_in[1];
  const float* Wq = (const float*)d_in[2];
  const float* bq = (const float*)d_in[3];
  const float* Wk = (const float*)d_in[4];
  const float* bk = (const float*)d_in[5];
  const float* Wv = (const float*)d_in[6];
  const float* bv = (const float*)d_in[7];
  const int* idx = (const int*)d_in[8];
  float* out = (float*)d_out;

  cudaFuncSetAttribute(mma_kernel<0>, cudaFuncAttributeMaxDynamicSharedMemorySize, SMTOT);
  cudaFuncSetAttribute(mma_kernel<1>, cudaFuncAttributeMaxDynamicSharedMemorySize, SMTOT);
  cudaFuncSetAttribute(mma_kernel<2>, cudaFuncAttributeMaxDynamicSharedMemorySize, SMTOT);
  cudaFuncSetAttribute(mma_kernel<3>, cudaFuncAttributeMaxDynamicSharedMemorySize, SMTOT);

  wsplit_kernel<<<dim3(256, 3), 1024>>>(Wq, Wk, Wv);
  xt_split_kernel<<<dim3(128, 16, BATCH), dim3(32, 8)>>>(in1, in2);
  mma_kernel<0><<<dim3(32, 12, BATCH), 256, SMTOT>>>(bq, bk, bv);
  vt_split_kernel<<<dim3(128, 16, BATCH), dim3(32, 8)>>>();
  vpart_kernel<<<dim3(4, BATCH), 512>>>();
  vmean_kernel<<<BATCH, 512>>>();
  gather_ks3_kernel<<<dim3(UTOP, BATCH), 192>>>(idx);
  mma_kernel<1><<<dim3(4, 32, BATCH), 256, SMTOT>>>(bq, bk, bv);
  topk_kernel<<<BATCH, 1024>>>();
  gather_qr3_kernel<<<dim3(UTOP, BATCH), 192>>>();
  mma_kernel<2><<<dim3(32, 4, BATCH), 256, SMTOT>>>(bq, bk, bv);
  softmax_kernel<<<BATCH * UTOP, 256>>>();
  mma_kernel<3><<<dim3(4, 4, BATCH), 256, SMTOT>>>(bq, bk, bv);
  assemble_kernel<<<dim3(LSP, BATCH), 128>>>(out);
}

// round 10
// speedup vs baseline: 2.0552x; 2.0552x over previous
#include <cuda_runtime.h>
#include <cuda_fp16.h>
#include <math.h>
#include <stdint.h>

#define BATCH 16
#define LSP   4096
#define DD    512
#define UTOP  450
#define SCALE 0.044194173824159216f
#define WSCL  256.0f
#define WSCLI (1.0f / 256.0f)
#define P2M   ((size_t)LSP * DD)
typedef uint32_t u32;

#define PITCHB  144        // 64 fp16 + 8 pad = 72 halves = 144B row pitch
#define PLANE_S 18432      // 128 rows * 144B
#define SMTOT   (4 * PLANE_S)

// ---------------- scratch ----------------
__device__ float  g_V[(size_t)BATCH * P2M];
__device__ __half g_Ws[3 * 2 * 262144];
__device__ __half g_Xt[(size_t)BATCH * 2 * P2M];
__device__ __half g_Qs[(size_t)BATCH * 2 * P2M];
__device__ __half g_Ksp[(size_t)BATCH * 2 * P2M];
__device__ __half g_Vt[(size_t)BATCH * 2 * P2M];
__device__ __half g_Kss[(size_t)BATCH * 2 * 262144];
__device__ __half g_Qrs[(size_t)BATCH * 2 * 262144];
__device__ __half g_Attn[(size_t)BATCH * 2 * P2M];
__device__ float  g_Scores[(size_t)BATCH * UTOP * LSP];
__device__ float  g_MpMax[BATCH * 4 * LSP];
__device__ float  g_MpSum[BATCH * 4 * LSP];
__device__ int    g_selrank[BATCH * LSP];
__device__ int    g_mtop[BATCH * UTOP];
__device__ float  g_Upd[(size_t)BATCH * UTOP * DD];
__device__ float  g_Vpart[BATCH * 4 * DD];
__device__ float  g_Vmean[BATCH * DD];

// ---------------- helpers ----------------
__device__ __forceinline__ void split2h(float x, __half& c0, __half& c1) {
  c0 = __float2half_rn(x);
  c1 = __float2half_rn(x - __half2float(c0));
}
__device__ __forceinline__ u32 smem_u32(const void* p) {
  u32 a;
  asm("{ .reg .u64 t; cvta.to.shared.u64 t, %1; cvt.u32.u64 %0, t; }" : "=r"(a) : "l"(p));
  return a;
}
__device__ __forceinline__ void ldm4(u32* r, u32 addr) {
  asm volatile("ldmatrix.sync.aligned.m8n8.x4.shared.b16 {%0,%1,%2,%3}, [%4];"
               : "=r"(r[0]), "=r"(r[1]), "=r"(r[2]), "=r"(r[3]) : "r"(addr));
}
__device__ __forceinline__ void mma16816(float* c, const u32* a, const u32* b) {
  asm volatile(
      "mma.sync.aligned.m16n8k16.row.col.f32.f16.f16.f32 "
      "{%0,%1,%2,%3}, {%4,%5,%6,%7}, {%8,%9}, {%0,%1,%2,%3};"
      : "+f"(c[0]), "+f"(c[1]), "+f"(c[2]), "+f"(c[3])
      : "r"(a[0]), "r"(a[1]), "r"(a[2]), "r"(a[3]), "r"(b[0]), "r"(b[1]));
}
__device__ __forceinline__ float fast_exp(float x) {
  x = fmaxf(x, -80.0f);
  float t = x * 1.4426950408889634f, r = rintf(t), f = t - r;
  float p = 1.5404e-4f;
  p = fmaf(p, f, 1.33336e-3f); p = fmaf(p, f, 9.61813e-3f);
  p = fmaf(p, f, 5.55041e-2f); p = fmaf(p, f, 2.40227e-1f);
  p = fmaf(p, f, 6.93147181e-1f); p = fmaf(p, f, 1.0f);
  return __int_as_float(__float_as_int(p) + (((int)r) << 23));
}

// ---------------- fp16 2-comp 3-combo mma.sync GEMM ----------------
// MODE 0 proj, 1 qks->M, 2 scores, 3 upd
template <int MODE>
__global__ void __launch_bounds__(256) mma_kernel(const float* __restrict__ bq,
                                                  const float* __restrict__ bk,
                                                  const float* __restrict__ bv) {
  extern __shared__ char smem[];
  const int tid = threadIdx.x, lane = tid & 31, wid = tid >> 5;
  const int wm = wid & 1, wn = wid >> 1;       // 2 x 4 warp grid
  const int b = blockIdx.z;
  constexpr int CI[3] = {0, 0, 1};
  constexpr int CJ[3] = {0, 1, 0};

  int rowA0, wsel = 0, nCh;
  size_t aPlane, bPlane, apit, bpit;
  const __half *Ab, *Bb;
  if (MODE == 0) {
    wsel = blockIdx.y >> 2; rowA0 = (blockIdx.y & 3) * 128;
    Ab = g_Ws + (size_t)wsel * 2 * 262144; aPlane = 262144; apit = 512;
    Bb = g_Xt + (size_t)b * 2 * P2M; bPlane = P2M; bpit = 512; nCh = 8;
  } else if (MODE == 1) {
    rowA0 = blockIdx.y * 128;
    Ab = g_Qs + (size_t)b * 2 * P2M; aPlane = P2M; apit = 512;
    Bb = g_Kss + (size_t)b * 2 * 262144; bPlane = 262144; bpit = 512; nCh = 8;
  } else if (MODE == 2) {
    rowA0 = blockIdx.y * 128;
    Ab = g_Qrs + (size_t)b * 2 * 262144; aPlane = 262144; apit = 512;
    Bb = g_Ksp + (size_t)b * 2 * P2M; bPlane = P2M; bpit = 512; nCh = 8;
  } else {
    rowA0 = blockIdx.y * 128;
    Ab = g_Attn + (size_t)b * 2 * P2M; aPlane = P2M; apit = 4096;
    Bb = g_Vt + (size_t)b * 2 * P2M; bPlane = P2M; bpit = 4096; nCh = 64;
  }
  const int rowB0 = blockIdx.x * 128;
  const u32 sb = smem_u32(smem);

  float acc[4][4][4] = {};
  const int srow = tid >> 1, shalf = tid & 1;

  for (int ch = 0; ch < nCh; ch++) {
    const int kt = ch * 64;
    #pragma unroll
    for (int c = 0; c < 2; c++) {
      const char* ga = (const char*)(Ab + (size_t)c * aPlane + (size_t)(rowA0 + srow) * apit + kt + shalf * 32);
      char* sa = smem + c * PLANE_S + srow * PITCHB + shalf * 64;
      const char* gb = (const char*)(Bb + (size_t)c * bPlane + (size_t)(rowB0 + srow) * bpit + kt + shalf * 32);
      char* sbp = smem + (2 + c) * PLANE_S + srow * PITCHB + shalf * 64;
      #pragma unroll
      for (int i = 0; i < 4; i++) {
        *(uint4*)(sa + i * 16) = *(const uint4*)(ga + i * 16);
        *(uint4*)(sbp + i * 16) = *(const uint4*)(gb + i * 16);
      }
    }
    __syncthreads();

    #pragma unroll
    for (int kk = 0; kk < 4; kk++) {
      const int k0 = kk * 16;
      u32 afr[2][4][4], bfr[2][4][2];
      #pragma unroll
      for (int c = 0; c < 2; c++) {
        #pragma unroll
        for (int mt = 0; mt < 4; mt++) {
          u32 ad = sb + c * PLANE_S + (wm * 64 + mt * 16 + (lane & 15)) * PITCHB +
                   k0 * 2 + (lane >> 4) * 16;
          ldm4(afr[c][mt], ad);
        }
        #pragma unroll
        for (int p = 0; p < 2; p++) {
          u32 bd = sb + (2 + c) * PLANE_S +
                   (wn * 32 + p * 16 + (lane & 7) + ((lane >> 4) & 1) * 8) * PITCHB +
                   k0 * 2 + ((lane >> 3) & 1) * 16;
          u32 t4[4]; ldm4(t4, bd);
          bfr[c][2 * p][0] = t4[0]; bfr[c][2 * p][1] = t4[1];
          bfr[c][2 * p + 1][0] = t4[2]; bfr[c][2 * p + 1][1] = t4[3];
        }
      }
      #pragma unroll
      for (int q = 0; q < 3; q++) {
        #pragma unroll
        for (int mt = 0; mt < 4; mt++)
          #pragma unroll
          for (int nt = 0; nt < 4; nt++)
            mma16816(acc[mt][nt], afr[CI[q]][mt], bfr[CJ[q]][nt]);
      }
    }
    __syncthreads();
  }

  const int qrow = lane >> 2, qcol = (lane & 3) * 2;

  if (MODE == 1) {
    float mx[8], sm[8];
    #pragma unroll
    for (int i = 0; i < 8; i++) { mx[i] = -3.0e38f; sm[i] = 0.f; }
    #pragma unroll
    for (int mt = 0; mt < 4; mt++)
      #pragma unroll
      for (int h = 0; h < 2; h++)
        #pragma unroll
        for (int nt = 0; nt < 4; nt++)
          #pragma unroll
          for (int e = 0; e < 2; e++) {
            int s = rowB0 + wn * 32 + nt * 8 + qcol + e;
            float v = acc[mt][nt][h * 2 + e];
            if (s < UTOP) { mx[mt * 2 + h] = fmaxf(mx[mt * 2 + h], v); sm[mt * 2 + h] += v; }
          }
    #pragma unroll
    for (int off = 1; off <= 2; off <<= 1)
      #pragma unroll
      for (int i = 0; i < 8; i++) {
        mx[i] = fmaxf(mx[i], __shfl_xor_sync(0xffffffffu, mx[i], off));
        sm[i] += __shfl_xor_sync(0xffffffffu, sm[i], off);
      }
    float* smax = (float*)smem;          // [128][4]
    float* ssum = smax + 512;
    if ((lane & 3) == 0) {
      #pragma unroll
      for (int mt = 0; mt < 4; mt++)
        #pragma unroll
        for (int h = 0; h < 2; h++) {
          int rl = wm * 64 + mt * 16 + qrow + h * 8;
          smax[rl * 4 + wn] = mx[mt * 2 + h];
          ssum[rl * 4 + wn] = sm[mt * 2 + h];
        }
    }
    __syncthreads();
    if (tid < 128) {
      float M1 = -3.0e38f, S = 0.f;
      #pragma unroll
      for (int j = 0; j < 4; j++) { M1 = fmaxf(M1, smax[tid * 4 + j]); S += ssum[tid * 4 + j]; }
      g_MpMax[((size_t)b * 4 + blockIdx.x) * LSP + rowA0 + tid] = M1;
      g_MpSum[((size_t)b * 4 + blockIdx.x) * LSP + rowA0 + tid] = S;
    }
    return;
  }

  #pragma unroll
  for (int mt = 0; mt < 4; mt++) {
    #pragma unroll
    for (int h = 0; h < 2; h++) {
      const int m = rowA0 + wm * 64 + mt * 16 + qrow + h * 8;
      float bias_v = 0.f;
      if (MODE == 0) bias_v = (wsel == 0 ? bq : wsel == 1 ? bk : bv)[m & 511];
      #pragma unroll
      for (int nt = 0; nt < 4; nt++) {
        const int col = rowB0 + wn * 32 + nt * 8 + qcol;
        float v0 = acc[mt][nt][h * 2 + 0];
        float v1 = acc[mt][nt][h * 2 + 1];
        if (MODE == 0) {
          v0 = v0 * WSCLI + bias_v; v1 = v1 * WSCLI + bias_v;
          size_t flat = (size_t)m * 4096 + col;
          if (wsel == 2) {
            *(float2*)(g_V + (size_t)b * P2M + flat) = make_float2(v0, v1);
          } else {
            __half* qp = (wsel == 0 ? g_Qs : g_Ksp) + (size_t)b * 2 * P2M;
            __half a0, a1, c0, c1;
            split2h(v0, a0, a1); split2h(v1, c0, c1);
            *(__half2*)(qp + flat) = __halves2half2(a0, c0);
            *(__half2*)(qp + P2M + flat) = __halves2half2(a1, c1);
          }
        } else if (MODE == 2) {
          if (m < UTOP)
            *(float2*)(g_Scores + ((size_t)b * UTOP + m) * LSP + col) =
                make_float2(v0 * SCALE, v1 * SCALE);
        } else {
          if (m < UTOP)
            *(float2*)(g_Upd + ((size_t)b * UTOP + m) * DD + col) = make_float2(v0, v1);
        }
      }
    }
  }
}

// ---------------- prep kernels ----------------
__global__ void wsplit_kernel(const float* __restrict__ Wq, const float* __restrict__ Wk,
                              const float* __restrict__ Wv) {
  int mat = blockIdx.y;
  int i = blockIdx.x * 1024 + threadIdx.x;
  const float* W = mat == 0 ? Wq : mat == 1 ? Wk : Wv;
  __half c0, c1; split2h(W[i] * WSCL, c0, c1);
  __half* o = g_Ws + (size_t)mat * 2 * 262144;
  o[i] = c0; o[262144 + i] = c1;
}

__global__ void xt_split_kernel(const float* __restrict__ in1, const float* __restrict__ in2) {
  __shared__ float t[32][33];
  int b = blockIdx.z, c0i = blockIdx.y * 32, sp0 = blockIdx.x * 32;
  for (int j = threadIdx.y; j < 32; j += 8) {
    int c = c0i + j;
    const float* s = (c < 256) ? in1 + ((size_t)b * 256 + c) * LSP
                               : in2 + ((size_t)b * 256 + (c - 256)) * LSP;
    t[j][threadIdx.x] = s[sp0 + threadIdx.x];
  }
  __syncthreads();
  __half* o = g_Xt + (size_t)b * 2 * P2M;
  for (int j = threadIdx.y; j < 32; j += 8) {
    size_t flat = (size_t)(sp0 + j) * 512 + c0i + threadIdx.x;
    __half a0, a1; split2h(t[threadIdx.x][j], a0, a1);
    o[flat] = a0; o[P2M + flat] = a1;
  }
}

__global__ void vt_split_kernel() {
  __shared__ float t[32][33];
  int b = blockIdx.z, l0 = blockIdx.x * 32, d0 = blockIdx.y * 32;
  const float* V = g_V + (size_t)b * P2M;
  for (int j = threadIdx.y; j < 32; j += 8)
    t[j][threadIdx.x] = V[(size_t)(l0 + j) * 512 + d0 + threadIdx.x];
  __syncthreads();
  __half* o = g_Vt + (size_t)b * 2 * P2M;
  for (int j = threadIdx.y; j < 32; j += 8) {
    size_t flat = (size_t)(d0 + j) * LSP + l0 + threadIdx.x;
    __half a0, a1; split2h(t[threadIdx.x][j], a0, a1);
    o[flat] = a0; o[P2M + flat] = a1;
  }
}

// full-row gathers: 128 thr = 2 comps x 64 thr x 16B = 1024B per 512-half row
__global__ void gather_ks2_kernel(const int* __restrict__ idx) {
  int b = blockIdx.y, s = blockIdx.x, t = threadIdx.x;
  int l = idx[s];
  int c = t >> 6, i = t & 63;
  const uint4* src = (const uint4*)(g_Ksp + ((size_t)b * 2 + c) * P2M + (size_t)l * 512);
  uint4* dst = (uint4*)(g_Kss + ((size_t)b * 2 + c) * 262144 + (size_t)s * 512);
  dst[i] = src[i];
}
__global__ void gather_qr2_kernel() {
  int b = blockIdx.y, s = blockIdx.x, t = threadIdx.x;
  int l = g_mtop[b * UTOP + s];
  int c = t >> 6, i = t & 63;
  const uint4* src = (const uint4*)(g_Qs + ((size_t)b * 2 + c) * P2M + (size_t)l * 512);
  uint4* dst = (uint4*)(g_Qrs + ((size_t)b * 2 + c) * 262144 + (size_t)s * 512);
  dst[i] = src[i];
}

// ---------------- topk (reduces MODE1 partials) ----------------
__global__ __launch_bounds__(1024) void topk_kernel() {
  const int b = blockIdx.x, tid = threadIdx.x;
  __shared__ unsigned long long keys[4096];
  for (int i = tid; i < 4096; i += 1024) {
    float mx = -3.0e38f, sm = 0.f;
    #pragma unroll
    for (int st = 0; st < 4; st++) {
      mx = fmaxf(mx, g_MpMax[((size_t)b * 4 + st) * LSP + i]);
      sm += g_MpSum[((size_t)b * 4 + st) * LSP + i];
    }
    float M = mx - sm * (1.0f / 4096.0f);
    unsigned u = __float_as_uint(M);
    u = (u & 0x80000000u) ? ~u : (u | 0x80000000u);
    keys[i] = ((unsigned long long)(~u) << 32) | (unsigned)i;
  }
  __syncthreads();
  for (int k = 2; k <= 4096; k <<= 1)
    for (int j = k >> 1; j > 0; j >>= 1) {
      for (int t = tid; t < 4096; t += 1024) {
        int ixj = t ^ j;
        if (ixj > t) {
          unsigned long long a = keys[t], c = keys[ixj];
          bool up = ((t & k) == 0);
          if ((a > c) == up) { keys[t] = c; keys[ixj] = a; }
        }
      }
      __syncthreads();
    }
  for (int i = tid; i < 4096; i += 1024) g_selrank[b * LSP + i] = -1;
  __syncthreads();
  if (tid < UTOP) {
    int l = (int)(unsigned)(keys[tid] & 0xffffffffu);
    g_selrank[b * LSP + l] = tid;
    g_mtop[b * UTOP + tid] = l;
  }
}

// ---------------- softmax + 2-comp fp16 attn split ----------------
__global__ __launch_bounds__(256) void softmax_kernel() {
  const int row = blockIdx.x, b = row / UTOP, u = row - b * UTOP;
  const float4* p = (const float4*)(g_Scores + (size_t)row * LSP);
  const int tid = threadIdx.x;
  __shared__ float red[256];
  float4 r[4];
  float m = -3.0e38f;
  #pragma unroll
  for (int i = 0; i < 4; i++) {
    r[i] = p[tid + i * 256];
    m = fmaxf(m, fmaxf(fmaxf(r[i].x, r[i].y), fmaxf(r[i].z, r[i].w)));
  }
  red[tid] = m; __syncthreads();
  for (int s = 128; s; s >>= 1) { if (tid < s) red[tid] = fmaxf(red[tid], red[tid + s]); __syncthreads(); }
  m = red[0]; __syncthreads();
  float sum = 0.f;
  #pragma unroll
  for (int i = 0; i < 4; i++) {
    r[i].x = fast_exp(r[i].x - m); r[i].y = fast_exp(r[i].y - m);
    r[i].z = fast_exp(r[i].z - m); r[i].w = fast_exp(r[i].w - m);
    sum += (r[i].x + r[i].y) + (r[i].z + r[i].w);
  }
  red[tid] = sum; __syncthreads();
  for (int s = 128; s; s >>= 1) { if (tid < s) red[tid] += red[tid + s]; __syncthreads(); }
  float inv = 1.0f / red[0];
  __half* a0 = g_Attn + (size_t)b * 2 * P2M + (size_t)u * LSP;
  __half* a1 = a0 + P2M;
  #pragma unroll
  for (int i = 0; i < 4; i++) {
    int c = (tid + i * 256) * 4;
    float v[4] = {r[i].x * inv, r[i].y * inv, r[i].z * inv, r[i].w * inv};
    __half lo[4], hi[4];
    #pragma unroll
    for (int k = 0; k < 4; k++) split2h(v[k], lo[k], hi[k]);
    *(__half2*)(a0 + c) = __halves2half2(lo[0], lo[1]);
    *(__half2*)(a0 + c + 2) = __halves2half2(lo[2], lo[3]);
    *(__half2*)(a1 + c) = __halves2half2(hi[0], hi[1]);
    *(__half2*)(a1 + c + 2) = __halves2half2(hi[2], hi[3]);
  }
}

// ---------------- V mean + assemble ----------------
__global__ __launch_bounds__(512) void vpart_kernel() {
  const int b = blockIdx.y, g = blockIdx.x, d = threadIdx.x;
  const float* base = g_V + (size_t)b * P2M + (size_t)(g * 1024) * 512 + d;
  float s0 = 0, s1 = 0, s2 = 0, s3 = 0;
  for (int l = 0; l < 1024; l += 4) {
    s0 += base[(size_t)(l + 0) * 512]; s1 += base[(size_t)(l + 1) * 512];
    s2 += base[(size_t)(l + 2) * 512]; s3 += base[(size_t)(l + 3) * 512];
  }
  g_Vpart[((size_t)b * 4 + g) * 512 + d] = (s0 + s1) + (s2 + s3);
}
__global__ __launch_bounds__(512) void vmean_kernel() {
  const int b = blockIdx.x, d = threadIdx.x;
  float s = 0;
  #pragma unroll
  for (int g = 0; g < 4; g++) s += g_Vpart[((size_t)b * 4 + g) * 512 + d];
  g_Vmean[b * 512 + d] = s * (1.0f / 4096.0f);
}
__global__ void assemble_kernel(float* __restrict__ out) {
  const int b = blockIdx.y, l = blockIdx.x;
  const int r = g_selrank[b * LSP + l];
  const float4* src = (r >= 0) ? (const float4*)(g_Upd + ((size_t)b * UTOP + r) * 512)
                               : (const float4*)(g_Vmean + (size_t)b * 512);
  float4* dst = (float4*)(out + ((size_t)b * LSP + l) * 512);
  dst[threadIdx.x] = src[threadIdx.x];
}

// ---------------- launch ----------------
extern "C" void kernel_launch(void* const* d_in, const int* in_sizes, int n_in,
                              void* d_out, int out_size) {
  const float* in1 = (const float*)d_in[0];
  const float* in2 = (const float*)d_in[1];
  const float* Wq = (const float*)d_in[2];
  const float* bq = (const float*)d_in[3];
  const float* Wk = (const float*)d_in[4];
  const float* bk = (const float*)d_in[5];
  const float* Wv = (const float*)d_in[6];
  const float* bv = (const float*)d_in[7];
  const int* idx = (const int*)d_in[8];
  float* out = (float*)d_out;

  cudaFuncSetAttribute(mma_kernel<0>, cudaFuncAttributeMaxDynamicSharedMemorySize, SMTOT);
  cudaFuncSetAttribute(mma_kernel<1>, cudaFuncAttributeMaxDynamicSharedMemorySize, SMTOT);
  cudaFuncSetAttribute(mma_kernel<2>, cudaFuncAttributeMaxDynamicSharedMemorySize, SMTOT);
  cudaFuncSetAttribute(mma_kernel<3>, cudaFuncAttributeMaxDynamicSharedMemorySize, SMTOT);

  wsplit_kernel<<<dim3(256, 3), 1024>>>(Wq, Wk, Wv);
  xt_split_kernel<<<dim3(128, 16, BATCH), dim3(32, 8)>>>(in1, in2);
  mma_kernel<0><<<dim3(32, 12, BATCH), 256, SMTOT>>>(bq, bk, bv);
  vt_split_kernel<<<dim3(128, 16, BATCH), dim3(32, 8)>>>();
  vpart_kernel<<<dim3(4, BATCH), 512>>>();
  vmean_kernel<<<BATCH, 512>>>();
  gather_ks2_kernel<<<dim3(UTOP, BATCH), 128>>>(idx);
  mma_kernel<1><<<dim3(4, 32, BATCH), 256, SMTOT>>>(bq, bk, bv);
  topk_kernel<<<BATCH, 1024>>>();
  gather_qr2_kernel<<<dim3(UTOP, BATCH), 128>>>();
  mma_kernel<2><<<dim3(32, 4, BATCH), 256, SMTOT>>>(bq, bk, bv);
  softmax_kernel<<<BATCH * UTOP, 256>>>();
  mma_kernel<3><<<dim3(4, 4, BATCH), 256, SMTOT>>>(bq, bk, bv);
  assemble_kernel<<<dim3(LSP, BATCH), 128>>>(out);
}